// round 4
// baseline (speedup 1.0000x reference)
#include <cuda_runtime.h>
#include <cuda_bf16.h>

// out[i,j] = sigmoid( sum_h W2[h]*relu(A[i,h]+B[j,h]) + b2 )
//   A = Z@W1[:D] + b1, B = Z@W1[D:].
// Identity: relu(a+b) = max(a,-b)+b  =>  sum = sum_h w*max(a,-b) + C_j.
#define NN 2048
#define DD 32
#define HH 64

__device__ float g_A [NN * HH];  // A[n][h]
__device__ float g_nB[NN * HH];  // -B[n][h]
__device__ float g_C [NN];       // C[j] = sum_h W2[h]*B[j,h]

typedef unsigned long long u64t;

__device__ __forceinline__ u64t fma_f32x2(u64t a, u64t b, u64t c) {
    u64t d;
    asm("fma.rn.f32x2 %0, %1, %2, %3;" : "=l"(d) : "l"(a), "l"(b), "l"(c));
    return d;
}
__device__ __forceinline__ u64t pack2(float lo, float hi) {
    u64t d;
    asm("mov.b64 %0, {%1, %2};" : "=l"(d) : "f"(lo), "f"(hi));
    return d;
}
// packed max via 2 scalar FMNMX (alu pipe) on float components, producing u64.
__device__ __forceinline__ u64t max2p(float alo, float ahi, float blo, float bhi) {
    u64t d;
    asm("{\n\t"
        ".reg .b32 dl, dh;\n\t"
        "max.f32 dl, %1, %3;\n\t"
        "max.f32 dh, %2, %4;\n\t"
        "mov.b64 %0, {dl, dh};\n\t"
        "}" : "=l"(d) : "f"(alo), "f"(ahi), "f"(blo), "f"(bhi));
    return d;
}

// ---------------------------------------------------------------------------
// Prep: A, -B, C.
// ---------------------------------------------------------------------------
__global__ void prep_kernel(const float* __restrict__ Z,
                            const float* __restrict__ W1,
                            const float* __restrict__ b1,
                            const float* __restrict__ W2) {
    __shared__ float zs[4][DD];
    __shared__ float cbuf[4][HH];
    int tid = threadIdx.x;
    int nblk = blockIdx.x * 4;
    if (tid < 4 * DD) {
        zs[tid >> 5][tid & 31] = Z[(nblk + (tid >> 5)) * DD + (tid & 31)];
    }
    __syncthreads();
    int local_n = tid >> 6;
    int h = tid & 63;
    int n = nblk + local_n;
    float sa = b1[h];
    float sb = 0.0f;
#pragma unroll
    for (int d = 0; d < DD; d++) {
        float z = zs[local_n][d];
        sa = fmaf(z, W1[d * HH + h], sa);
        sb = fmaf(z, W1[(DD + d) * HH + h], sb);
    }
    g_A [n * HH + h] = sa;
    g_nB[n * HH + h] = -sb;
    cbuf[local_n][h] = sb * W2[h];
    __syncthreads();
    if (tid < 4) {
        float c = 0.0f;
#pragma unroll
        for (int k = 0; k < HH; k++) c += cbuf[tid][k];
        g_C[nblk + tid] = c;
    }
}

// ---------------------------------------------------------------------------
// Pair kernel: 64x64 tile, 256 threads, 4x4 pairs/thread (i=ty+16*ii,
// j=tx+16*jj). 4h-step with LDS.128 batched loads: 9 loads per 96 math
// instructions; loads batched at step top so math covers LDS latency.
// SROW=68 floats (272B): 16B-aligned for LDS.128; B-row wavefront = 256B
// distinct data = crossbar floor.
// ---------------------------------------------------------------------------
#define SROW 68

__global__ __launch_bounds__(256, 3)
void pair_kernel(const float* __restrict__ W2,
                 const float* __restrict__ b2,
                 float* __restrict__ out) {
    __shared__ float As[64 * SROW];
    __shared__ float Bs[64 * SROW];   // holds -B
    __shared__ float ws[HH];
    __shared__ float Cs[64];

    int tid = threadIdx.x;
    int bi = blockIdx.y * 64;
    int bj = blockIdx.x * 64;

    for (int idx = tid; idx < 64 * HH; idx += 256) {
        int r = idx >> 6;
        int h = idx & 63;
        As[r * SROW + h] = g_A [(bi + r) * HH + h];
        Bs[r * SROW + h] = g_nB[(bj + r) * HH + h];
    }
    if (tid < HH) ws[tid] = W2[tid];
    if (tid >= 128 && tid < 192) Cs[tid - 128] = g_C[bj + (tid - 128)];
    __syncthreads();

    int tx = tid & 15;   // j lane
    int ty = tid >> 4;   // i lane

    u64t acc[4][4];
#pragma unroll
    for (int ii = 0; ii < 4; ii++)
#pragma unroll
        for (int jj = 0; jj < 4; jj++) acc[ii][jj] = 0ull;

    const float* arow0 = &As[ty * SROW];
    const float* brow0 = &Bs[tx * SROW];

#pragma unroll 2
    for (int h = 0; h < HH; h += 4) {
        // Batched LDS.128 loads for this 4h step.
        float4 wv = *(const float4*)&ws[h];
        u64t wlo = pack2(wv.x, wv.y);
        u64t whi = pack2(wv.z, wv.w);
        float4 a4[4], b4[4];
#pragma unroll
        for (int ii = 0; ii < 4; ii++)
            a4[ii] = *(const float4*)&arow0[ii * 16 * SROW + h];
#pragma unroll
        for (int jj = 0; jj < 4; jj++)
            b4[jj] = *(const float4*)&brow0[jj * 16 * SROW + h];

#pragma unroll
        for (int jj = 0; jj < 4; jj++) {
#pragma unroll
            for (int ii = 0; ii < 4; ii++) {
                u64t t0 = max2p(a4[ii].x, a4[ii].y, b4[jj].x, b4[jj].y);
                acc[ii][jj] = fma_f32x2(t0, wlo, acc[ii][jj]);
                u64t t1 = max2p(a4[ii].z, a4[ii].w, b4[jj].z, b4[jj].w);
                acc[ii][jj] = fma_f32x2(t1, whi, acc[ii][jj]);
            }
        }
    }

    float bias = b2[0];
#pragma unroll
    for (int ii = 0; ii < 4; ii++) {
        int gi = bi + ty + ii * 16;
#pragma unroll
        for (int jj = 0; jj < 4; jj++) {
            int gj = bj + tx + jj * 16;
            float2 v = *(float2*)&acc[ii][jj];
            float x = v.x + v.y + Cs[tx + jj * 16] + bias;
            float e = __expf(-x);
            float s = __fdividef(1.0f, 1.0f + e);
            out[gi * NN + gj] = s;   // coalesced across tx
        }
    }
}

extern "C" void kernel_launch(void* const* d_in, const int* in_sizes, int n_in,
                              void* d_out, int out_size) {
    const float* Z  = (const float*)d_in[0];
    const float* W1 = (const float*)d_in[1];
    const float* b1 = (const float*)d_in[2];
    const float* W2 = (const float*)d_in[3];
    const float* b2 = (const float*)d_in[4];
    float* out = (float*)d_out;

    prep_kernel<<<NN / 4, 256>>>(Z, W1, b1, W2);
    dim3 grid(NN / 64, NN / 64);
    pair_kernel<<<grid, 256>>>(W2, b2, out);
}